// round 1
// baseline (speedup 1.0000x reference)
#include <cuda_runtime.h>
#include <math.h>

#define NB   4
#define SQ   2048
#define SKV  4096
#define EDIM 1024
#define CDIM 512
#define HEADS 16
#define HDIM  64

// Scratch (static device arrays: allowed; no allocation)
__device__ float g_cond[(size_t)NB * SQ * EDIM];     // 32 MB: condition @ Wc^T + bc
__device__ float g_attout[(size_t)NB * SKV * EDIM];  // 64 MB: attention output

// ---------------------------------------------------------------------------
// GEMM: C[m][n] = sum_k A[m][k] * W[n][k] + bias[n]
// A: (M,K) row-major, W: (N,K) row-major. M%128==0, N%128==0, K%8==0 assumed.
// 128x128 tile, BK=8, 256 threads, 8x8 per thread.
// ---------------------------------------------------------------------------
__global__ __launch_bounds__(256) void gemm_abt(
    const float* __restrict__ A, const float* __restrict__ W,
    const float* __restrict__ bias, float* __restrict__ C,
    int M, int N, int K)
{
    const int BM = 128, BN = 128, BK = 8;
    __shared__ float As[BK][BM];
    __shared__ float Ws[BK][BN];

    const int tid = threadIdx.x;
    const int mBase = blockIdx.y * BM;
    const int nBase = blockIdx.x * BN;

    const int loadRow = tid >> 1;        // 0..127
    const int loadCol = (tid & 1) * 4;   // 0 or 4

    const int tr = tid >> 4;             // 0..15 (row group)
    const int tc = tid & 15;             // 0..15 (col group)

    float acc[8][8];
    #pragma unroll
    for (int i = 0; i < 8; i++)
        #pragma unroll
        for (int j = 0; j < 8; j++) acc[i][j] = 0.f;

    const float* Aptr = A + (size_t)(mBase + loadRow) * K + loadCol;
    const float* Wptr = W + (size_t)(nBase + loadRow) * K + loadCol;

    for (int k0 = 0; k0 < K; k0 += BK) {
        float4 av = *(const float4*)(Aptr + k0);
        float4 wv = *(const float4*)(Wptr + k0);
        As[loadCol + 0][loadRow] = av.x;
        As[loadCol + 1][loadRow] = av.y;
        As[loadCol + 2][loadRow] = av.z;
        As[loadCol + 3][loadRow] = av.w;
        Ws[loadCol + 0][loadRow] = wv.x;
        Ws[loadCol + 1][loadRow] = wv.y;
        Ws[loadCol + 2][loadRow] = wv.z;
        Ws[loadCol + 3][loadRow] = wv.w;
        __syncthreads();

        #pragma unroll
        for (int k = 0; k < BK; ++k) {
            float rm[8], rn[8];
            *(float4*)&rm[0] = *(const float4*)&As[k][tr * 8];
            *(float4*)&rm[4] = *(const float4*)&As[k][tr * 8 + 4];
            *(float4*)&rn[0] = *(const float4*)&Ws[k][tc * 8];
            *(float4*)&rn[4] = *(const float4*)&Ws[k][tc * 8 + 4];
            #pragma unroll
            for (int i = 0; i < 8; i++)
                #pragma unroll
                for (int j = 0; j < 8; j++)
                    acc[i][j] += rm[i] * rn[j];
        }
        __syncthreads();
    }

    // Epilogue: add bias, store as float4
    #pragma unroll
    for (int i = 0; i < 8; i++) {
        const int m = mBase + tr * 8 + i;
        float* Crow = C + (size_t)m * N + nBase + tc * 8;
        #pragma unroll
        for (int j = 0; j < 8; j += 4) {
            float4 o;
            o.x = acc[i][j + 0] + bias[nBase + tc * 8 + j + 0];
            o.y = acc[i][j + 1] + bias[nBase + tc * 8 + j + 1];
            o.z = acc[i][j + 2] + bias[nBase + tc * 8 + j + 2];
            o.w = acc[i][j + 3] + bias[nBase + tc * 8 + j + 3];
            *(float4*)(Crow + j) = o;
        }
    }
}

// ---------------------------------------------------------------------------
// Per-position heads-attention. One block (256 threads) per (n, t),
// pos = n*SKV + t, 16384 blocks total.
//   cq row: t even -> queries[n, t/2], t odd -> g_cond[n, (t-1)/2]
//   att[h][e] = (1/8) * dot64(cq[h], k[e]); masked; softmax over e; out = att @ v
// ---------------------------------------------------------------------------
__global__ __launch_bounds__(256) void attn_kernel(
    const float* __restrict__ queries, const float* __restrict__ keys,
    const float* __restrict__ values, const int* __restrict__ mask)
{
    __shared__ float cq[1024];
    __shared__ float kT[64 * 17];   // transposed K row with pad: kT[d*17 + e]
    __shared__ float vv[1024];
    __shared__ float sc[16][16];

    const int pos = blockIdx.x;          // 0..16383
    const int n = pos >> 12;             // / SKV
    const int t = pos & (SKV - 1);
    const int tid = threadIdx.x;

    const float* cqrow = (t & 1)
        ? (g_cond  + (size_t)(n * SQ + (t >> 1)) * EDIM)
        : (queries + (size_t)(n * SQ + (t >> 1)) * EDIM);
    const float* krow = keys   + (size_t)pos * EDIM;
    const float* vrow = values + (size_t)pos * EDIM;

    // Coalesced loads: 256 threads x float4 = 1024 floats each
    ((float4*)cq)[tid] = ((const float4*)cqrow)[tid];
    ((float4*)vv)[tid] = ((const float4*)vrow)[tid];
    {
        float4 kv = ((const float4*)krow)[tid];
        int g = tid * 4;                 // element index: e = g>>6, d = g&63
        #pragma unroll
        for (int i = 0; i < 4; i++) {
            int gg = g + i;
            kT[(gg & 63) * 17 + (gg >> 6)] = (&kv.x)[i];
        }
    }
    __syncthreads();

    // Scores: thread (h = tid>>4, e = tid&15)
    const int h = tid >> 4;
    const int e = tid & 15;
    float s = 0.f;
    #pragma unroll
    for (int d = 0; d < HDIM; d++)
        s += cq[h * HDIM + d] * kT[d * 17 + e];
    s *= 0.125f;  // 1/sqrt(64)

    const int mv = mask[(size_t)pos * (HEADS * HEADS) + h * 16 + e];
    if (mv == 0) s = -1e20f;
    sc[h][e] = s;
    __syncthreads();

    // Row softmax (each thread redundantly reduces its 16-wide row)
    float mx = -INFINITY;
    #pragma unroll
    for (int j = 0; j < 16; j++) mx = fmaxf(mx, sc[h][j]);
    float denom = 0.f;
    #pragma unroll
    for (int j = 0; j < 16; j++) denom += expf(sc[h][j] - mx);
    float p = expf(s - mx) / denom;
    __syncthreads();
    sc[h][e] = p;
    __syncthreads();

    // out[h][d] = sum_e p[h][e] * v[e][d]; thread -> 4 consecutive outputs
    const int obase = tid * 4;
    const int oh = obase >> 6;           // head of this output group
    const int od = obase & 63;
    float a0 = 0.f, a1 = 0.f, a2 = 0.f, a3 = 0.f;
    #pragma unroll
    for (int j = 0; j < 16; j++) {
        float a = sc[oh][j];
        const float* vj = vv + j * HDIM + od;
        a0 += a * vj[0];
        a1 += a * vj[1];
        a2 += a * vj[2];
        a3 += a * vj[3];
    }
    float4 o = make_float4(a0, a1, a2, a3);
    ((float4*)(g_attout + (size_t)pos * EDIM))[tid] = o;
}

// ---------------------------------------------------------------------------
// Launch
// ---------------------------------------------------------------------------
extern "C" void kernel_launch(void* const* d_in, const int* in_sizes, int n_in,
                              void* d_out, int out_size)
{
    const float* values    = (const float*)d_in[0];
    const float* keys      = (const float*)d_in[1];
    const float* queries   = (const float*)d_in[2];
    const int*   mask      = (const int*)  d_in[3];
    const float* condition = (const float*)d_in[4];
    const float* Wc        = (const float*)d_in[5];
    const float* bc        = (const float*)d_in[6];
    const float* Wo        = (const float*)d_in[7];
    const float* bo        = (const float*)d_in[8];
    float* out = (float*)d_out;

    float* cond_ptr = nullptr;
    float* attout_ptr = nullptr;
    cudaGetSymbolAddress((void**)&cond_ptr, g_cond);
    cudaGetSymbolAddress((void**)&attout_ptr, g_attout);

    // 1) cond = condition @ Wc^T + bc : M=8192, N=1024, K=512
    {
        dim3 grid(EDIM / 128, (NB * SQ) / 128);
        gemm_abt<<<grid, 256>>>(condition, Wc, bc, cond_ptr, NB * SQ, EDIM, CDIM);
    }

    // 2) per-position attention -> g_attout : 16384 blocks
    attn_kernel<<<NB * SKV, 256>>>(queries, keys, values, mask);

    // 3) out = g_attout @ Wo^T + bo : M=16384, N=1024, K=1024
    {
        dim3 grid(EDIM / 128, (NB * SKV) / 128);
        gemm_abt<<<grid, 256>>>(attout_ptr, Wo, bo, out, NB * SKV, EDIM, EDIM);
    }
}